// round 14
// baseline (speedup 1.0000x reference)
#include <cuda_runtime.h>
#include <cuda_fp16.h>

// GatheringLoss — R14: B fragments pre-formatted in GLOBAL memory (exact
// m16n8k16 ldmatrix-equivalent layout). Mainloop = LDG.128 + 2 MMA, no smem B,
// no cp.async, no mainloop barriers. 128thr/4warp CTAs, 6 CTAs/SM (24 warps).
// Each warp scans all 1024 keys for its 16 rows; approx top-2 -> exact rescore.
// out = [kg (65536) | vg (65536)]

#define T_TOTAL 65536
#define M_KEYS  1024
#define C_DIM   128
#define BM      64
#define THREADS 128
#define SAB     272                 // A smem row stride (bytes)
#define SM_TOTAL 17408              // A tile only

// bfrag[(pg*8 + ks)*32 + lane] : uint4 = {b0,b1,b2,b3} for key pair-group pg
// (16 keys), k-step ks (16 dims).  b0/b1 = ntile 2*pg, b2/b3 = ntile 2*pg+1.
__device__ uint4 g_bfrag[64 * 8 * 32];

__device__ __forceinline__ unsigned smem_u32(const void* p) {
    unsigned a;
    asm("{ .reg .u64 t; cvta.to.shared.u64 t, %1; cvt.u32.u64 %0, t; }" : "=r"(a) : "l"(p));
    return a;
}

#define LDSM_X4(r0, r1, r2, r3, a)                                             \
    asm volatile("ldmatrix.sync.aligned.m8n8.x4.shared.b16 {%0,%1,%2,%3}, [%4];" \
                 : "=r"(r0), "=r"(r1), "=r"(r2), "=r"(r3) : "r"(a))

__device__ __forceinline__ void mma_f16(float* d, const unsigned* a,
                                        unsigned b0, unsigned b1) {
    asm("mma.sync.aligned.m16n8k16.row.col.f32.f16.f16.f32 "
        "{%0,%1,%2,%3}, {%4,%5,%6,%7}, {%8,%9}, {%0,%1,%2,%3};"
        : "+f"(d[0]), "+f"(d[1]), "+f"(d[2]), "+f"(d[3])
        : "r"(a[0]), "r"(a[1]), "r"(a[2]), "r"(a[3]), "r"(b0), "r"(b1));
}

#define UPD(s1, i1, s2, i2, v, n)                          \
    do { if ((v) > (s1)) { s2 = s1; i2 = i1; s1 = (v); i1 = (n); } \
         else if ((v) > (s2)) { s2 = (v); i2 = (n); } } while (0)

__device__ __forceinline__ void merge2(float& s1, int& i1, float& s2, int& i2,
                                       float t1, int j1, float t2, int j2) {
    if (t1 > s1 || (t1 == s1 && j1 < i1)) {
        float ns2; int ni2;
        if (s1 > t2 || (s1 == t2 && i1 < j2)) { ns2 = s1; ni2 = i1; }
        else                                  { ns2 = t2; ni2 = j2; }
        s1 = t1; i1 = j1; s2 = ns2; i2 = ni2;
    } else if (t1 > s2 || (t1 == s2 && j1 < i2)) {
        s2 = t1; i2 = j1;
    }
}

// ---- prep: keys -> fp16 fragment layout in global ----
__global__ void prep_bfrag_kernel(const float* __restrict__ keys) {
    int i = blockIdx.x * blockDim.x + threadIdx.x;   // 16384 uint4 slots
    if (i >= 64 * 8 * 32) return;
    int lane = i & 31;
    int ks   = (i >> 5) & 7;
    int pg   = i >> 8;
    int n0 = pg * 16 + (lane >> 2);
    int k0 = ks * 16 + (lane & 3) * 2;
    const float* kb = keys;
    __half2 b0 = __floats2half2_rn(kb[n0 * C_DIM + k0],       kb[n0 * C_DIM + k0 + 1]);
    __half2 b1 = __floats2half2_rn(kb[n0 * C_DIM + k0 + 8],   kb[n0 * C_DIM + k0 + 9]);
    __half2 b2 = __floats2half2_rn(kb[(n0 + 8) * C_DIM + k0],     kb[(n0 + 8) * C_DIM + k0 + 1]);
    __half2 b3 = __floats2half2_rn(kb[(n0 + 8) * C_DIM + k0 + 8], kb[(n0 + 8) * C_DIM + k0 + 9]);
    uint4 v;
    v.x = *(unsigned*)&b0; v.y = *(unsigned*)&b1;
    v.z = *(unsigned*)&b2; v.w = *(unsigned*)&b3;
    g_bfrag[i] = v;
}

__global__ __launch_bounds__(THREADS, 6)
void gathering_loss_kernel(const float* __restrict__ q,
                           const float* __restrict__ r,
                           const float* __restrict__ keys,
                           const float* __restrict__ values,
                           float* __restrict__ out)
{
    extern __shared__ char smem[];
    const unsigned sb = smem_u32(smem);
    const int tid  = threadIdx.x;
    const int lane = tid & 31;
    const int wid  = tid >> 5;          // 0..3
    const int row0 = blockIdx.x * BM;

    // ---- A tile: q rows -> fp16 smem [m][k], stride 272B ----
    {
        const float4* q4 = (const float4*)(q + (size_t)row0 * C_DIM);
        #pragma unroll
        for (int it = 0; it < (BM * C_DIM / 4) / THREADS; ++it) {
            int i = tid + it * THREADS;
            int m  = i >> 5;
            int k4 = (i & 31) << 2;
            float4 v = q4[i];
            __half2 h01 = __floats2half2_rn(v.x, v.y);
            __half2 h23 = __floats2half2_rn(v.z, v.w);
            char* p = smem + m * SAB + k4 * 2;
            *(__half2*)(p)     = h01;
            *(__half2*)(p + 4) = h23;
        }
    }
    __syncthreads();

    // ---- persistent A fragments (32 regs): warp owns rows wid*16 .. +15 ----
    unsigned ahi[8][4];
    {
        int amat = lane >> 3;
        unsigned apart = sb + (unsigned)(wid * 16 + (lane & 7) + ((amat & 1) << 3)) * SAB
                       + ((amat >> 1) << 4);
        #pragma unroll
        for (int ks = 0; ks < 8; ++ks)
            LDSM_X4(ahi[ks][0], ahi[ks][1], ahi[ks][2], ahi[ks][3], apart + ks * 32);
    }

    // ---- full key scan: 64 pair-groups x 8 ksteps, LDG.128 fragments ----
    float s1a = -3.402823466e38f, s2a = -3.402823466e38f;   // row gid
    float s1b = -3.402823466e38f, s2b = -3.402823466e38f;   // row gid+8
    int i1a = 0, i2a = 0, i1b = 0, i2b = 0;

    const uint4* __restrict__ bptr = g_bfrag + lane;

    #pragma unroll 2
    for (int pg = 0; pg < 64; ++pg) {
        float acc0[4] = {0.f, 0.f, 0.f, 0.f};   // ntile 2*pg
        float acc1[4] = {0.f, 0.f, 0.f, 0.f};   // ntile 2*pg+1
        const uint4* bp = bptr + pg * 256;
        #pragma unroll
        for (int ks = 0; ks < 8; ++ks) {
            uint4 b = bp[ks * 32];
            mma_f16(acc0, ahi[ks], b.x, b.y);
            mma_f16(acc1, ahi[ks], b.z, b.w);
        }
        // cols: ntile0 -> nb0, nb0+1 ; ntile1 -> nb0+8, nb0+9 (ascending order)
        int nb0 = pg * 16 + (lane & 3) * 2;
        float mxa = fmaxf(fmaxf(acc0[0], acc0[1]), fmaxf(acc1[0], acc1[1]));
        if (mxa > s2a) {
            UPD(s1a, i1a, s2a, i2a, acc0[0], nb0);
            UPD(s1a, i1a, s2a, i2a, acc0[1], nb0 + 1);
            UPD(s1a, i1a, s2a, i2a, acc1[0], nb0 + 8);
            UPD(s1a, i1a, s2a, i2a, acc1[1], nb0 + 9);
        }
        float mxb = fmaxf(fmaxf(acc0[2], acc0[3]), fmaxf(acc1[2], acc1[3]));
        if (mxb > s2b) {
            UPD(s1b, i1b, s2b, i2b, acc0[2], nb0);
            UPD(s1b, i1b, s2b, i2b, acc0[3], nb0 + 1);
            UPD(s1b, i1b, s2b, i2b, acc1[2], nb0 + 8);
            UPD(s1b, i1b, s2b, i2b, acc1[3], nb0 + 9);
        }
    }

    // ---- quad merge (lanes l^1, l^2 share the same rows) ----
    #pragma unroll
    for (int off = 1; off <= 2; off <<= 1) {
        float t1 = __shfl_xor_sync(0xffffffffu, s1a, off);
        int   j1 = __shfl_xor_sync(0xffffffffu, i1a, off);
        float t2 = __shfl_xor_sync(0xffffffffu, s2a, off);
        int   j2 = __shfl_xor_sync(0xffffffffu, i2a, off);
        merge2(s1a, i1a, s2a, i2a, t1, j1, t2, j2);
        t1 = __shfl_xor_sync(0xffffffffu, s1b, off);
        j1 = __shfl_xor_sync(0xffffffffu, i1b, off);
        t2 = __shfl_xor_sync(0xffffffffu, s2b, off);
        j2 = __shfl_xor_sync(0xffffffffu, i2b, off);
        merge2(s1b, i1b, s2b, i2b, t1, j1, t2, j2);
    }

    // cand: per-row (idx1, idx2) of the CTA's 64 rows (A smem reused; no warp
    // reads A after the persistent fragment load)
    int* ci = (int*)smem;               // [64][2]
    if ((lane & 3) == 0) {
        int ra = wid * 16 + (lane >> 2);
        ci[ra * 2 + 0]       = i1a;  ci[ra * 2 + 1]       = i2a;
        ci[(ra + 8) * 2 + 0] = i1b;  ci[(ra + 8) * 2 + 1] = i2b;
    }
    __syncthreads();

    // ---- epilogue: 2 threads/row; exact fp32 rescore of 2 candidates + losses ----
    {
        int row  = tid >> 1;             // 0..63
        int half = tid & 1;
        int grow = row0 + row;
        int c1 = ci[row * 2 + 0];
        int c2 = ci[row * 2 + 1];

        const float4* qp = (const float4*)(q    + (size_t)grow * C_DIM + half * 64);
        const float4* ka = (const float4*)(keys + (size_t)c1   * C_DIM + half * 64);
        const float4* kb = (const float4*)(keys + (size_t)c2   * C_DIM + half * 64);
        float sa = 0.f, sc = 0.f;
        #pragma unroll
        for (int c = 0; c < 16; ++c) {
            float4 a = qp[c], x = ka[c], y = kb[c];
            sa = fmaf(a.x, x.x, sa); sa = fmaf(a.y, x.y, sa);
            sa = fmaf(a.z, x.z, sa); sa = fmaf(a.w, x.w, sa);
            sc = fmaf(a.x, y.x, sc); sc = fmaf(a.y, y.y, sc);
            sc = fmaf(a.z, y.z, sc); sc = fmaf(a.w, y.w, sc);
        }
        sa += __shfl_xor_sync(0xffffffffu, sa, 1);
        sc += __shfl_xor_sync(0xffffffffu, sc, 1);
        int bi = (sc > sa || (sc == sa && c2 < c1)) ? c2 : c1;

        const float4* kp = (const float4*)(keys   + (size_t)bi   * C_DIM + half * 64);
        const float4* rp = (const float4*)(r      + (size_t)grow * C_DIM + half * 64);
        const float4* vp = (const float4*)(values + (size_t)bi   * C_DIM + half * 64);
        float sk = 0.f, sv = 0.f;
        #pragma unroll
        for (int c = 0; c < 16; ++c) {
            float4 a = qp[c], b = kp[c];
            float d;
            d = a.x - b.x; sk = fmaf(d, d, sk);
            d = a.y - b.y; sk = fmaf(d, d, sk);
            d = a.z - b.z; sk = fmaf(d, d, sk);
            d = a.w - b.w; sk = fmaf(d, d, sk);
            float4 e = rp[c], f = vp[c];
            d = e.x - f.x; sv = fmaf(d, d, sv);
            d = e.y - f.y; sv = fmaf(d, d, sv);
            d = e.z - f.z; sv = fmaf(d, d, sv);
            d = e.w - f.w; sv = fmaf(d, d, sv);
        }
        sk += __shfl_xor_sync(0xffffffffu, sk, 1);
        sv += __shfl_xor_sync(0xffffffffu, sv, 1);
        if (half == 0) out[grow]           = sk;
        else           out[T_TOTAL + grow] = sv;
    }
}

extern "C" void kernel_launch(void* const* d_in, const int* in_sizes, int n_in,
                              void* d_out, int out_size)
{
    const float* q      = (const float*)d_in[0];
    const float* r      = (const float*)d_in[1];
    const float* keys   = (const float*)d_in[2];
    const float* values = (const float*)d_in[3];
    float* out = (float*)d_out;

    prep_bfrag_kernel<<<(64 * 8 * 32 + 255) / 256, 256>>>(keys);

    cudaFuncSetAttribute(gathering_loss_kernel,
                         cudaFuncAttributeMaxDynamicSharedMemorySize, SM_TOTAL);
    gathering_loss_kernel<<<T_TOTAL / BM, THREADS, SM_TOTAL>>>(q, r, keys, values, out);
}